// round 1
// baseline (speedup 1.0000x reference)
#include <cuda_runtime.h>

// Problem constants
#define B       128
#define T       256
#define H       1024
#define NG      4096     // 4*H gate columns
#define KC      32       // k-chunk staged per inner pass
#define THREADS 256
#define CTAS    128
#define JPC     8        // h-columns owned per CTA
#define NCOLS   32       // gate columns per CTA (4 gates x JPC)

// Persistent state (static device globals: allocation-free per harness rules)
__device__ float g_h[2][B * H];                 // double-buffered hidden state
__device__ unsigned int g_bar_arrive = 0;
__device__ volatile unsigned int g_bar_gen = 0;

__device__ __forceinline__ void grid_barrier() {
    __syncthreads();
    __threadfence();   // gpu-scope: pushes stores to L2, flushes L1D (CCTL.IVALL)
    if (threadIdx.x == 0) {
        unsigned int gen = g_bar_gen;
        if (atomicAdd(&g_bar_arrive, 1u) == CTAS - 1) {
            g_bar_arrive = 0;
            __threadfence();
            g_bar_gen = gen + 1;
        } else {
            while (g_bar_gen == gen) { }
        }
    }
    __syncthreads();
}

// Packed fp32x2 FMA (sm_103a): doubles fp32 FMA throughput vs scalar FFMA
#define FMA2(d, a, bb, c) asm("fma.rn.f32x2 %0, %1, %2, %3;" : "=l"(d) : "l"(a), "l"(bb), "l"(c))
#define PACK2(d, lo, hi)  asm("mov.b64 %0, {%1, %2};" : "=l"(d) : "f"(lo), "f"(hi))
#define UNPACK2(lo, hi, s) asm("mov.b64 {%0, %1}, %2;" : "=f"(lo), "=f"(hi) : "l"(s))

// Dynamic SMEM layout (floats):
//   Usl   [1024][32]      32768   U slice, resident all 256 steps
//   hT    [32][132]        4224   transposed h chunk (k-major, padded)
//   zt    [128][33]        4224   z tile for epilogue gate exchange
//   csm   [128*8]          1024   cell state (persistent per CTA)
//   ssm   [128*4]           512   seq[:, t, :] staging
//   Wsl   [4][32]           128   W slice
//   bsl   [32]               32   bias slice
#define SM_FLOATS (32768 + 4224 + 4224 + 1024 + 512 + 128 + 32)

__global__ void __launch_bounds__(THREADS, 1)
lstm_persistent_kernel(const float* __restrict__ seq,
                       const float* __restrict__ W,
                       const float* __restrict__ U,
                       const float* __restrict__ bias,
                       float* __restrict__ out,
                       int write_extras)
{
    extern __shared__ float smem[];
    float* Usl = smem;                         // 32768
    float* hT  = Usl + H * NCOLS;              // 4224
    float* zt  = hT + KC * 132;                // 4224
    float* csm = zt + 128 * 33;                // 1024
    float* ssm = csm + B * JPC;                // 512
    float* Wsl = ssm + B * 4;                  // 128
    float* bsl = Wsl + 4 * NCOLS;              // 32

    const int tid = threadIdx.x;
    const int cta = blockIdx.x;
    const int j0  = cta * JPC;

    // ---- one-time prologue: cache U/W/b slices, zero c and h0 slice ----
    for (int idx = tid; idx < H * NCOLS; idx += THREADS) {
        int k = idx >> 5, cc = idx & 31;
        int gcol = (cc >> 3) * H + j0 + (cc & 7);
        Usl[idx] = U[(size_t)k * NG + gcol];
    }
    if (tid < 4 * NCOLS) {
        int f = tid >> 5, cc = tid & 31;
        int gcol = (cc >> 3) * H + j0 + (cc & 7);
        Wsl[tid] = W[f * NG + gcol];
    }
    if (tid < NCOLS) {
        int gcol = (tid >> 3) * H + j0 + (tid & 7);
        bsl[tid] = bias[gcol];
    }
    for (int idx = tid; idx < B * JPC; idx += THREADS) {
        csm[idx] = 0.0f;
        int b = idx >> 3, jj = idx & 7;
        __stcg(&g_h[0][b * H + j0 + jj], 0.0f);
    }
    grid_barrier();

    const int mt = tid >> 4;          // 0..15 : rows 8*mt .. 8*mt+7
    const int nt = tid & 15;          // 0..15 : cols 2*nt, 2*nt+1
    const int sb   = tid & 127;       // staging: batch row
    const int half = tid >> 7;        // staging: k half (0/1)

    const size_t OFF_H = (size_t)B * T * H;
    const size_t OFF_C = OFF_H + (size_t)B * H;

    for (int t = 0; t < T; ++t) {
        const int r = t & 1, w = r ^ 1;

        // stage seq[:, t, :] (contiguous float4 per batch row)
        if (tid < B) {
            float4 s4 = *((const float4*)seq + ((size_t)tid * T + t));
            ssm[tid * 4 + 0] = s4.x; ssm[tid * 4 + 1] = s4.y;
            ssm[tid * 4 + 2] = s4.z; ssm[tid * 4 + 3] = s4.w;
        }

        unsigned long long acc[4][2];
        #pragma unroll
        for (int p = 0; p < 4; ++p) { acc[p][0] = 0ull; acc[p][1] = 0ull; }

        // ---- GEMM: z[128 x 32] += h[128 x 1024] * Uslice[1024 x 32] ----
        for (int kt = 0; kt < H / KC; ++kt) {
            __syncthreads();   // protect hT from previous chunk's readers
            {
                const float4* src = (const float4*)(g_h[r] + (size_t)sb * H + kt * KC + half * 16);
                #pragma unroll
                for (int i = 0; i < 4; ++i) {
                    float4 v = __ldcg(&src[i]);     // L2 (fresh), skip L1
                    int kk = half * 16 + i * 4;
                    hT[(kk + 0) * 132 + sb] = v.x;
                    hT[(kk + 1) * 132 + sb] = v.y;
                    hT[(kk + 2) * 132 + sb] = v.z;
                    hT[(kk + 3) * 132 + sb] = v.w;
                }
            }
            __syncthreads();
            const float* Ub = Usl + kt * KC * NCOLS + 2 * nt;
            #pragma unroll
            for (int k = 0; k < KC; ++k) {
                const ulonglong2* hrow = (const ulonglong2*)(hT + k * 132 + 8 * mt);
                ulonglong2 hA = hrow[0];     // rows 8mt+0..3 as two f32x2
                ulonglong2 hB = hrow[1];     // rows 8mt+4..7
                float2 uv = *(const float2*)(Ub + k * NCOLS);
                unsigned long long u0, u1;
                PACK2(u0, uv.x, uv.x);
                PACK2(u1, uv.y, uv.y);
                FMA2(acc[0][0], hA.x, u0, acc[0][0]);
                FMA2(acc[0][1], hA.x, u1, acc[0][1]);
                FMA2(acc[1][0], hA.y, u0, acc[1][0]);
                FMA2(acc[1][1], hA.y, u1, acc[1][1]);
                FMA2(acc[2][0], hB.x, u0, acc[2][0]);
                FMA2(acc[2][1], hB.x, u1, acc[2][1]);
                FMA2(acc[3][0], hB.y, u0, acc[3][0]);
                FMA2(acc[3][1], hB.y, u1, acc[3][1]);
            }
        }

        // ---- scatter z tile to SMEM for gate exchange ----
        #pragma unroll
        for (int p = 0; p < 4; ++p) {
            float lo, hi;
            UNPACK2(lo, hi, acc[p][0]);
            zt[(8 * mt + 2 * p) * 33 + 2 * nt]     = lo;
            zt[(8 * mt + 2 * p + 1) * 33 + 2 * nt] = hi;
            UNPACK2(lo, hi, acc[p][1]);
            zt[(8 * mt + 2 * p) * 33 + 2 * nt + 1]     = lo;
            zt[(8 * mt + 2 * p + 1) * 33 + 2 * nt + 1] = hi;
        }
        __syncthreads();

        // ---- epilogue: x_proj + bias + gates + state update (4 items/thread) ----
        #pragma unroll
        for (int q = 0; q < 4; ++q) {
            int idx = tid * 4 + q;            // idx = b*8 + jj
            int b = idx >> 3, jj = idx & 7;
            float zg4[4];
            #pragma unroll
            for (int g = 0; g < 4; ++g) {
                int cc = g * 8 + jj;
                float z = zt[b * 33 + cc] + bsl[cc];
                #pragma unroll
                for (int f = 0; f < 4; ++f)
                    z += ssm[b * 4 + f] * Wsl[f * NCOLS + cc];
                zg4[g] = z;
            }
            float ig = 1.0f / (1.0f + __expf(-zg4[0]));   // input gate
            float fg = 1.0f / (1.0f + __expf(-zg4[1]));   // forget gate
            float gg = fmaxf(zg4[2], 0.0f);               // candidate (relu)
            float og = 1.0f / (1.0f + __expf(-zg4[3]));   // output gate
            float cn = fg * csm[idx] + ig * gg;
            csm[idx] = cn;
            float hn = og * fmaxf(cn, 0.0f);              // relu on cell output
            int j = j0 + jj;
            __stcg(&g_h[w][(size_t)b * H + j], hn);
            out[((size_t)b * T + t) * H + j] = hn;
            if (write_extras && t == T - 1) {
                out[OFF_H + (size_t)b * H + j] = hn;      // h_last
                out[OFF_C + (size_t)b * H + j] = cn;      // c_last
            }
        }
        grid_barrier();   // all h_new visible before next step's reads
    }
}

extern "C" void kernel_launch(void* const* d_in, const int* in_sizes, int n_in,
                              void* d_out, int out_size)
{
    const float* seq  = (const float*)d_in[0];   // [128,256,4]
    const float* W    = (const float*)d_in[1];   // [4,4096]
    const float* U    = (const float*)d_in[2];   // [1024,4096]
    const float* bias = (const float*)d_in[3];   // [4096]
    float* out = (float*)d_out;

    long long need = (long long)B * T * H + 2LL * B * H;
    int write_extras = ((long long)out_size >= need) ? 1 : 0;

    size_t smem_bytes = (size_t)SM_FLOATS * sizeof(float);   // ~171.6 KB
    cudaFuncSetAttribute(lstm_persistent_kernel,
                         cudaFuncAttributeMaxDynamicSharedMemorySize,
                         (int)smem_bytes);

    lstm_persistent_kernel<<<CTAS, THREADS, smem_bytes>>>(seq, W, U, bias, out,
                                                          write_extras);
}

// round 3
// speedup vs baseline: 4.0099x; 4.0099x over previous
#include <cuda_runtime.h>
#include <cuda_bf16.h>
#include <cstdint>

#define B       128
#define T       256
#define H       1024
#define NG      4096
#define THREADS 256
#define NWARP   8
#define CTAS    128
#define JPC     8
#define KCH     64          // k per chunk
#define NCHUNK  16

// ---- persistent device state ----
__device__ __nv_bfloat16 g_hhi[2][B * H];
__device__ __nv_bfloat16 g_hlo[2][B * H];
__device__ unsigned int g_bar_arrive = 0;
__device__ volatile unsigned int g_bar_gen = 0;

// ---- SMEM layout (bytes) ----
// U^T hi/lo: [32 n][1024 k] bf16, row stride 2064B (pad => 4-bank stride, conflict-free)
#define U_RSTRIDE 2064
#define OFF_UHI 0
#define OFF_ULO 66048
// A tiles: 2 slots x (hi,lo) x [128 rows][64 k] bf16, row stride 144B
#define A_RSTRIDE 144
#define A_TILE  18432
#define OFF_A   132096                   // slot s: hi = OFF_A + s*36864, lo = +18432
#define OFF_SSM 205824                   // seq staging 128*4 f32 = 2048
#define OFF_W   207872                   // 4*32 f32
#define OFF_BS  208384                   // 32 f32
#define SMEM_TOTAL 208512

__device__ __forceinline__ uint32_t smem_u32(const void* p) {
    uint32_t a;
    asm("{ .reg .u64 t; cvta.to.shared.u64 t, %1; cvt.u32.u64 %0, t; }"
        : "=r"(a) : "l"(p));
    return a;
}

#define CP16(dst, src) asm volatile("cp.async.cg.shared.global [%0], [%1], 16;" :: "r"(dst), "l"(src))
#define CPCOMMIT()     asm volatile("cp.async.commit_group;" ::: "memory")
#define CPWAIT(n)      asm volatile("cp.async.wait_group %0;" :: "n"(n) : "memory")

#define LDSM_X4(r0, r1, r2, r3, a) \
    asm volatile("ldmatrix.sync.aligned.m8n8.x4.shared.b16 {%0,%1,%2,%3}, [%4];" \
                 : "=r"(r0), "=r"(r1), "=r"(r2), "=r"(r3) : "r"(a))

#define MMA_BF16(d, a0, a1, a2, a3, b0, b1) \
    asm volatile("mma.sync.aligned.m16n8k16.row.col.f32.bf16.bf16.f32 " \
                 "{%0,%1,%2,%3}, {%4,%5,%6,%7}, {%8,%9}, {%0,%1,%2,%3};" \
                 : "+f"((d)[0]), "+f"((d)[1]), "+f"((d)[2]), "+f"((d)[3]) \
                 : "r"(a0), "r"(a1), "r"(a2), "r"(a3), "r"(b0), "r"(b1))

__device__ __forceinline__ void grid_barrier() {
    __syncthreads();
    __threadfence();
    if (threadIdx.x == 0) {
        unsigned int gen = g_bar_gen;
        if (atomicAdd(&g_bar_arrive, 1u) == CTAS - 1) {
            g_bar_arrive = 0;
            __threadfence();
            g_bar_gen = gen + 1;
        } else {
            while (g_bar_gen == gen) { }
        }
    }
    __syncthreads();
}

// stage one 64-k chunk of h (hi + lo) into an A slot
__device__ __forceinline__ void load_chunk(uint32_t ahib, uint32_t alob,
                                           const __nv_bfloat16* __restrict__ hhi,
                                           const __nv_bfloat16* __restrict__ hlo,
                                           int c, int tid) {
#pragma unroll
    for (int i = 0; i < 4; ++i) {
        int seg = tid + i * THREADS;          // 1024 segs per tile
        int row = seg >> 3, sc = seg & 7;
        uint32_t d = row * A_RSTRIDE + sc * 16;
        const __nv_bfloat16* s = hhi + row * H + c * KCH + sc * 8;
        CP16(ahib + d, s);
        CP16(alob + d, hlo + row * H + c * KCH + sc * 8);
        (void)s;
    }
    CPCOMMIT();
}

__global__ void __launch_bounds__(THREADS, 1)
lstm_hmma_kernel(const float* __restrict__ seq,
                 const float* __restrict__ W,
                 const float* __restrict__ U,
                 const float* __restrict__ bias,
                 float* __restrict__ out,
                 int write_extras)
{
    extern __shared__ __align__(1024) uint8_t smem[];
    const uint32_t sbase = smem_u32(smem);
    const int tid = threadIdx.x;
    const int wid = tid >> 5;
    const int lid = tid & 31;
    const int cta = blockIdx.x;
    const int j0  = cta * JPC;

    float* ssm = (float*)(smem + OFF_SSM);
    float* Wsl = (float*)(smem + OFF_W);
    float* bsl = (float*)(smem + OFF_BS);

    // ---------------- prologue ----------------
    // U slice -> U^T bf16 hi/lo: row n (gate*8+jj), k contiguous
    for (int idx = tid; idx < 32 * H; idx += THREADS) {
        int k = idx >> 5, n = idx & 31;                 // consecutive tid -> consecutive n
        int gcol = ((n >> 3) << 10) + j0 + (n & 7);
        float v = U[(size_t)k * NG + gcol];
        __nv_bfloat16 hi = __float2bfloat16(v);
        __nv_bfloat16 lo = __float2bfloat16(v - __bfloat162float(hi));
        *(__nv_bfloat16*)(smem + OFF_UHI + n * U_RSTRIDE + k * 2) = hi;
        *(__nv_bfloat16*)(smem + OFF_ULO + n * U_RSTRIDE + k * 2) = lo;
    }
    if (tid < 4 * 32) {
        int f = tid >> 5, cc = tid & 31;
        Wsl[tid] = W[f * NG + ((cc >> 3) << 10) + j0 + (cc & 7)];
    }
    if (tid < 32)
        bsl[tid] = bias[((tid >> 3) << 10) + j0 + (tid & 7)];
    for (int idx = tid; idx < B * JPC; idx += THREADS) {
        int b = idx >> 3, jj = idx & 7;
        g_hhi[0][b * H + j0 + jj] = __float2bfloat16(0.0f);
        g_hlo[0][b * H + j0 + jj] = __float2bfloat16(0.0f);
    }
    grid_barrier();

    // ---- per-lane fragment geometry ----
    const int lr  = lid & 7;
    const int grp = lid >> 3;
    // A ldmatrix: mat0 rows0-7/klo, mat1 rows8-15/klo, mat2 rows0-7/khi, mat3 rows8-15/khi
    const uint32_t aoff = (uint32_t)((16 * wid + (grp & 1) * 8 + lr) * A_RSTRIDE + (grp >> 1) * 16);
    // B ldmatrix: mat0 n0-7/klo, mat1 n0-7/khi, mat2 n8-15/klo, mat3 n8-15/khi
    const uint32_t boff = (uint32_t)(((grp >> 1) * 8 + lr) * U_RSTRIDE + (grp & 1) * 16);
    const uint32_t uhib = sbase + OFF_UHI;
    const uint32_t ulob = sbase + OFF_ULO;

    uint32_t aHi[2], aLo[2];
#pragma unroll
    for (int s = 0; s < 2; ++s) {
        aHi[s] = sbase + OFF_A + s * (2 * A_TILE);
        aLo[s] = aHi[s] + A_TILE;
    }

    // epilogue lane mapping
    const int rq = lid >> 2;            // 0..7
    const int jp = (lid & 3) * 2;       // jj pair base

    float c_reg[4];
#pragma unroll
    for (int q = 0; q < 4; ++q) c_reg[q] = 0.0f;

    const size_t OFF_HL = (size_t)B * T * H;
    const size_t OFF_CL = OFF_HL + (size_t)B * H;

    for (int t = 0; t < T; ++t) {
        const int r = t & 1, wb = r ^ 1;
        const __nv_bfloat16* hhi = g_hhi[r];
        const __nv_bfloat16* hlo = g_hlo[r];

        if (tid < B) {
            float4 s4 = __ldg((const float4*)seq + ((size_t)tid * T + t));
            ssm[tid * 4 + 0] = s4.x; ssm[tid * 4 + 1] = s4.y;
            ssm[tid * 4 + 2] = s4.z; ssm[tid * 4 + 3] = s4.w;
        }

        float acc[4][4];
#pragma unroll
        for (int n = 0; n < 4; ++n)
#pragma unroll
            for (int q = 0; q < 4; ++q) acc[n][q] = 0.0f;

        load_chunk(aHi[0], aLo[0], hhi, hlo, 0, tid);

        for (int c = 0; c < NCHUNK; ++c) {
            const int sl = c & 1;
            if (c + 1 < NCHUNK) {
                load_chunk(aHi[sl ^ 1], aLo[sl ^ 1], hhi, hlo, c + 1, tid);
                CPWAIT(1);
            } else {
                CPWAIT(0);
            }
            __syncthreads();

#pragma unroll
            for (int q = 0; q < 4; ++q) {
                const uint32_t kb = (uint32_t)(c * 128 + q * 32);
                uint32_t ah0, ah1, ah2, ah3, al0, al1, al2, al3;
                LDSM_X4(ah0, ah1, ah2, ah3, aHi[sl] + aoff + q * 32);
                LDSM_X4(al0, al1, al2, al3, aLo[sl] + aoff + q * 32);
                uint32_t bh[8], bl[8];
                LDSM_X4(bh[0], bh[1], bh[2], bh[3], uhib + boff + kb);
                LDSM_X4(bh[4], bh[5], bh[6], bh[7], uhib + boff + 16 * U_RSTRIDE + kb);
                LDSM_X4(bl[0], bl[1], bl[2], bl[3], ulob + boff + kb);
                LDSM_X4(bl[4], bl[5], bl[6], bl[7], ulob + boff + 16 * U_RSTRIDE + kb);
                // pass 1: A_hi * B_hi
                MMA_BF16(acc[0], ah0, ah1, ah2, ah3, bh[0], bh[1]);
                MMA_BF16(acc[1], ah0, ah1, ah2, ah3, bh[2], bh[3]);
                MMA_BF16(acc[2], ah0, ah1, ah2, ah3, bh[4], bh[5]);
                MMA_BF16(acc[3], ah0, ah1, ah2, ah3, bh[6], bh[7]);
                // pass 2: A_hi * B_lo
                MMA_BF16(acc[0], ah0, ah1, ah2, ah3, bl[0], bl[1]);
                MMA_BF16(acc[1], ah0, ah1, ah2, ah3, bl[2], bl[3]);
                MMA_BF16(acc[2], ah0, ah1, ah2, ah3, bl[4], bl[5]);
                MMA_BF16(acc[3], ah0, ah1, ah2, ah3, bl[6], bl[7]);
                // pass 3: A_lo * B_hi
                MMA_BF16(acc[0], al0, al1, al2, al3, bh[0], bh[1]);
                MMA_BF16(acc[1], al0, al1, al2, al3, bh[2], bh[3]);
                MMA_BF16(acc[2], al0, al1, al2, al3, bh[4], bh[5]);
                MMA_BF16(acc[3], al0, al1, al2, al3, bh[6], bh[7]);
            }
            __syncthreads();   // slot consumed; safe to overwrite next iter
        }

        // ---- epilogue (register-resident, no exchange) ----
        // cell k: row = 16*wid + rq + (k>=2)*8, jj = jp + (k&1)
        // z for gate g of cell k = acc[g][k]
#pragma unroll
        for (int k = 0; k < 4; ++k) {
            const int b  = 16 * wid + rq + ((k >> 1) << 3);
            const int jj = jp + (k & 1);
            float zg[4];
            const float s0 = ssm[b * 4 + 0], s1 = ssm[b * 4 + 1];
            const float s2 = ssm[b * 4 + 2], s3 = ssm[b * 4 + 3];
#pragma unroll
            for (int g = 0; g < 4; ++g) {
                const int cc = g * 8 + jj;
                zg[g] = acc[g][k] + bsl[cc]
                      + s0 * Wsl[cc] + s1 * Wsl[32 + cc]
                      + s2 * Wsl[64 + cc] + s3 * Wsl[96 + cc];
            }
            float ig = 1.0f / (1.0f + __expf(-zg[0]));
            float fg = 1.0f / (1.0f + __expf(-zg[1]));
            float gg = fmaxf(zg[2], 0.0f);
            float og = 1.0f / (1.0f + __expf(-zg[3]));
            float cn = fg * c_reg[k] + ig * gg;
            c_reg[k] = cn;
            float hv = og * fmaxf(cn, 0.0f);

            out[((size_t)b * T + t) * H + j0 + jj] = hv;
            __nv_bfloat16 hh = __float2bfloat16(hv);
            __nv_bfloat16 hl = __float2bfloat16(hv - __bfloat162float(hh));
            g_hhi[wb][(size_t)b * H + j0 + jj] = hh;
            g_hlo[wb][(size_t)b * H + j0 + jj] = hl;

            if (write_extras && t == T - 1) {
                out[OFF_HL + (size_t)b * H + j0 + jj] = hv;
                out[OFF_CL + (size_t)b * H + j0 + jj] = cn;
            }
        }
        grid_barrier();
    }
}

extern "C" void kernel_launch(void* const* d_in, const int* in_sizes, int n_in,
                              void* d_out, int out_size)
{
    const float* seq  = (const float*)d_in[0];   // [128,256,4]
    const float* W    = (const float*)d_in[1];   // [4,4096]
    const float* U    = (const float*)d_in[2];   // [1024,4096]
    const float* bias = (const float*)d_in[3];   // [4096]
    float* out = (float*)d_out;

    long long need = (long long)B * T * H + 2LL * B * H;
    int write_extras = ((long long)out_size >= need) ? 1 : 0;

    cudaFuncSetAttribute(lstm_hmma_kernel,
                         cudaFuncAttributeMaxDynamicSharedMemorySize, SMEM_TOTAL);
    lstm_hmma_kernel<<<CTAS, THREADS, SMEM_TOTAL>>>(seq, W, U, bias, out,
                                                    write_extras);
}